// round 1
// baseline (speedup 1.0000x reference)
#include <cuda_runtime.h>

#define NN 20000      // nodes
#define NE 160000     // edges
#define TE 320000     // 2E edge-rows
#define HH 128

// ---------------- scratch (static __device__, no allocs) ----------------
__device__ __align__(128) float s_ew2 [(size_t)TE * 128];   // er @ W2
__device__ __align__(128) float s_a0  [(size_t)NN * 128];   // nr @ W0
__device__ __align__(128) float s_a1  [(size_t)NN * 128];   // nr @ W1
__device__ __align__(128) float s_pre1[(size_t)TE * 128];   // lvl1 pre-act
__device__ __align__(128) float s_nacc[(size_t)NN * 128];   // node scatter accum
__device__ __align__(128) float s_nin [(size_t)NN * 128];
__device__ __align__(128) float s_np1 [(size_t)NN * 256];
__device__ __align__(128) float s_np2 [(size_t)NN * 128];
__device__ __align__(128) float s_ein [(size_t)TE * 256];
__device__ __align__(128) float s_ep1 [(size_t)TE * 256];
__device__ __align__(128) float s_ep2 [(size_t)TE * 128];
__device__ float s_sum[5 * 256];
__device__ float s_sq [5 * 256];
__device__ int   s_u[NE];
__device__ int   s_v[NE];
__device__ int   g_is64;

// ---------------- helpers ----------------
__global__ void k_zero() {
    size_t stride = (size_t)gridDim.x * blockDim.x;
    size_t i0 = (size_t)blockIdx.x * blockDim.x + threadIdx.x;
    size_t n = (size_t)NN * 128;
    for (size_t i = i0; i < n; i += stride) s_nacc[i] = 0.0f;
    if (i0 < 5 * 256) { s_sum[i0] = 0.0f; s_sq[i0] = 0.0f; }
}

// edge_index may be int64 (high words all 0) or int32. Detect.
__global__ void k_detect(const int* __restrict__ ei32) {
    if (threadIdx.x == 0 && blockIdx.x == 0) {
        int nz = 0;
        for (int i = 0; i < 256; i++) nz |= ei32[2 * i + 1];
        g_is64 = (nz == 0) ? 1 : 0;
    }
}

__global__ void k_decode(const void* __restrict__ ei) {
    int e = blockIdx.x * blockDim.x + threadIdx.x;
    if (e >= NE) return;
    if (g_is64) {
        const long long* p = (const long long*)ei;
        s_u[e] = (int)p[e];
        s_v[e] = (int)p[NE + e];
    } else {
        const int* p = (const int*)ei;
        s_u[e] = p[e];
        s_v[e] = p[NE + e];
    }
}

// ---------------- generic fp32 GEMM, 128x128 tile, BK=16, 8x8/thread ----------------
// C[M,NC] = A[M,K] @ B[K,NC]; optional column sum/sumsq accumulation (for BN stats).
__global__ __launch_bounds__(256) void k_gemm(
    const float* __restrict__ A, const float* __restrict__ Bm,
    float* __restrict__ C, int M, int K, int NC,
    float* __restrict__ sumO, float* __restrict__ sqO)
{
    __shared__ float As[16][128];
    __shared__ float Bs[16][128];
    const int tid = threadIdx.x;
    const int tx = tid & 15;       // col group (8 cols each)
    const int ty = tid >> 4;       // row group (8 rows each)
    const int mBase = blockIdx.x * 128;
    const int nBase = blockIdx.y * 128;

    float acc[8][8];
#pragma unroll
    for (int i = 0; i < 8; i++)
#pragma unroll
        for (int j = 0; j < 8; j++) acc[i][j] = 0.0f;

    for (int k0 = 0; k0 < K; k0 += 16) {
        // load A tile (128 rows x 16 k), transposed into As[k][m]; OOB rows -> 0
#pragma unroll
        for (int i = tid; i < 512; i += 256) {
            int row = i >> 2;
            int kq  = (i & 3) << 2;
            int gm  = mBase + row;
            float4 a = make_float4(0.f, 0.f, 0.f, 0.f);
            if (gm < M) a = *(const float4*)(A + (size_t)gm * K + k0 + kq);
            As[kq + 0][row] = a.x; As[kq + 1][row] = a.y;
            As[kq + 2][row] = a.z; As[kq + 3][row] = a.w;
        }
        // load B tile (16 k x 128 n)
#pragma unroll
        for (int i = tid; i < 512; i += 256) {
            int kr = i >> 5;
            int nc = (i & 31) << 2;
            *(float4*)&Bs[kr][nc] =
                *(const float4*)(Bm + (size_t)(k0 + kr) * NC + nBase + nc);
        }
        __syncthreads();
#pragma unroll
        for (int k = 0; k < 16; k++) {
            float a[8], b[8];
#pragma unroll
            for (int i = 0; i < 8; i++) a[i] = As[k][ty * 8 + i];
#pragma unroll
            for (int j = 0; j < 8; j++) b[j] = Bs[k][tx * 8 + j];
#pragma unroll
            for (int i = 0; i < 8; i++)
#pragma unroll
                for (int j = 0; j < 8; j++) acc[i][j] += a[i] * b[j];
        }
        __syncthreads();
    }

    // epilogue: store + per-thread column partial sums (OOB rows are exactly 0)
    float cs[8], cq[8];
#pragma unroll
    for (int j = 0; j < 8; j++) { cs[j] = 0.f; cq[j] = 0.f; }
#pragma unroll
    for (int i = 0; i < 8; i++) {
        int gm = mBase + ty * 8 + i;
        bool valid = gm < M;
#pragma unroll
        for (int j = 0; j < 8; j++) {
            float v = acc[i][j];
            cs[j] += v; cq[j] += v * v;
            if (valid) C[(size_t)gm * NC + nBase + tx * 8 + j] = v;
        }
    }
    if (sumO) {
#pragma unroll
        for (int j = 0; j < 8; j++) { As[ty][tx * 8 + j] = cs[j]; Bs[ty][tx * 8 + j] = cq[j]; }
        __syncthreads();
#pragma unroll
        for (int s = 8; s > 0; s >>= 1) {
            if (ty < s) {
#pragma unroll
                for (int j = 0; j < 8; j++) {
                    As[ty][tx * 8 + j] += As[ty + s][tx * 8 + j];
                    Bs[ty][tx * 8 + j] += Bs[ty + s][tx * 8 + j];
                }
            }
            __syncthreads();
        }
        if (ty == 0) {
#pragma unroll
            for (int j = 0; j < 8; j++) {
                atomicAdd(sumO + nBase + tx * 8 + j, As[0][tx * 8 + j]);
                atomicAdd(sqO  + nBase + tx * 8 + j, Bs[0][tx * 8 + j]);
            }
        }
    }
}

// pre1[2e]   = A0[u]+A0[v]+A1[u]+EW2[2e]
// pre1[2e+1] = A0[u]+A0[v]+A1[v]+EW2[2e+1]; accumulate BN stats (slot 0)
__global__ void k_combine(const float* __restrict__ ew2) {
    int c = threadIdx.x;  // 128
    float ls = 0.f, lq = 0.f;
    for (int e = blockIdx.x; e < NE; e += gridDim.x) {
        int u = s_u[e], v = s_v[e];
        float a0u = s_a0[(size_t)u * 128 + c], a0v = s_a0[(size_t)v * 128 + c];
        float a1u = s_a1[(size_t)u * 128 + c], a1v = s_a1[(size_t)v * 128 + c];
        float base = a0u + a0v;
        size_t r0 = (size_t)(2 * e) * 128, r1 = (size_t)(2 * e + 1) * 128;
        float p0 = base + a1u + ew2[r0 + c];
        float p1 = base + a1v + ew2[r1 + c];
        s_pre1[r0 + c] = p0;
        s_pre1[r1 + c] = p1;
        ls += p0 + p1; lq += p0 * p0 + p1 * p1;
    }
    atomicAdd(&s_sum[c], ls);
    atomicAdd(&s_sq[c],  lq);
}

// BN+ReLU on pre1, then scatter: nacc[u] += (1+eps12)*h0 + (h0+h1), sym for v
__global__ void k_scatter(const float* __restrict__ g, const float* __restrict__ b,
                          const float* __restrict__ eps12p) {
    int c = threadIdx.x;
    float mean = s_sum[c] * (1.0f / TE);
    float var  = s_sq[c]  * (1.0f / TE) - mean * mean;
    float sc = g[c] * rsqrtf(var + 1e-5f);
    float sh = b[c] - mean * sc;
    float e12 = 1.0f + *eps12p;
    for (int e = blockIdx.x; e < NE; e += gridDim.x) {
        int u = s_u[e], v = s_v[e];
        size_t r0 = (size_t)(2 * e) * 128, r1 = (size_t)(2 * e + 1) * 128;
        float h0 = fmaxf(s_pre1[r0 + c] * sc + sh, 0.f);
        float h1 = fmaxf(s_pre1[r1 + c] * sc + sh, 0.f);
        float ds = h0 + h1;
        atomicAdd(&s_nacc[(size_t)u * 128 + c], e12 * h0 + ds);
        atomicAdd(&s_nacc[(size_t)v * 128 + c], e12 * h1 + ds);
    }
}

__global__ void k_nin(const float* __restrict__ nr, const float* __restrict__ eps11p) {
    float e11 = 1.0f + *eps11p;
    size_t stride = (size_t)gridDim.x * blockDim.x;
    size_t n = (size_t)NN * 128;
    for (size_t i = (size_t)blockIdx.x * blockDim.x + threadIdx.x; i < n; i += stride)
        s_nin[i] = e11 * nr[i] + s_nacc[i];
}

// edge_in rows: [fh(e), sh(r)] with fh=(1+eps2)*0.5*(er0+er1)+nr[u]+nr[v], sh=(1+eps2)*er[r]+nr[atom]
__global__ void k_ein(const float* __restrict__ er, const float* __restrict__ nr,
                      const float* __restrict__ eps2p) {
    int c = threadIdx.x;
    float e2 = 1.0f + *eps2p;
    for (int e = blockIdx.x; e < NE; e += gridDim.x) {
        int u = s_u[e], v = s_v[e];
        size_t er0i = (size_t)(2 * e) * 128, er1i = (size_t)(2 * e + 1) * 128;
        float er0 = er[er0i + c], er1 = er[er1i + c];
        float nru = nr[(size_t)u * 128 + c], nrv = nr[(size_t)v * 128 + c];
        float fh = e2 * 0.5f * (er0 + er1) + nru + nrv;
        size_t r0 = (size_t)(2 * e) * 256, r1 = (size_t)(2 * e + 1) * 256;
        s_ein[r0 + c] = fh;
        s_ein[r1 + c] = fh;
        s_ein[r0 + 128 + c] = e2 * er0 + nru;
        s_ein[r1 + 128 + c] = e2 * er1 + nrv;
    }
}

// dst = relu(src*scale + shift), column stats from sum/sq (cols is a power of 2)
__global__ void k_bnapply(const float* __restrict__ src, float* __restrict__ dst,
                          int rows, int colMask,
                          const float* __restrict__ sum, const float* __restrict__ sq,
                          const float* __restrict__ g, const float* __restrict__ b) {
    float inv = 1.0f / (float)rows;
    size_t n = (size_t)rows * (colMask + 1);
    size_t stride = (size_t)gridDim.x * blockDim.x;
    for (size_t i = (size_t)blockIdx.x * blockDim.x + threadIdx.x; i < n; i += stride) {
        int c = (int)(i & (size_t)colMask);
        float mean = sum[c] * inv;
        float var  = sq[c] * inv - mean * mean;
        float sc = g[c] * rsqrtf(var + 1e-5f);
        float v = src[i] * sc + (b[c] - mean * sc);
        dst[i] = fmaxf(v, 0.f);
    }
}

// ---------------- launch ----------------
extern "C" void kernel_launch(void* const* d_in, const int* in_sizes, int n_in,
                              void* d_out, int out_size) {
    const float* nr      = (const float*)d_in[0];
    const float* er      = (const float*)d_in[1];
    const void*  ei      = d_in[2];
    const float* lift_w1 = (const float*)d_in[3];
    const float* lift_g1 = (const float*)d_in[4];
    const float* lift_b1 = (const float*)d_in[5];
    const float* lift_w2 = (const float*)d_in[6];
    const float* lift_g2 = (const float*)d_in[7];
    const float* lift_b2 = (const float*)d_in[8];
    const float* lvl1_w  = (const float*)d_in[9];
    const float* lvl1_g  = (const float*)d_in[10];
    const float* lvl1_b  = (const float*)d_in[11];
    const float* lvl2_w1 = (const float*)d_in[12];
    const float* lvl2_g1 = (const float*)d_in[13];
    const float* lvl2_b1 = (const float*)d_in[14];
    const float* lvl2_w2 = (const float*)d_in[15];
    const float* lvl2_g2 = (const float*)d_in[16];
    const float* lvl2_b2 = (const float*)d_in[17];
    const float* eps11   = (const float*)d_in[18];
    const float* eps12   = (const float*)d_in[19];
    const float* eps2    = (const float*)d_in[20];

    float* out_node = (float*)d_out;
    float* out_edge = out_node + (size_t)NN * HH;

    float *p_ew2, *p_a0, *p_a1, *p_nin, *p_np1, *p_np2, *p_ein, *p_ep1, *p_ep2, *p_sum, *p_sq;
    cudaGetSymbolAddress((void**)&p_ew2, s_ew2);
    cudaGetSymbolAddress((void**)&p_a0,  s_a0);
    cudaGetSymbolAddress((void**)&p_a1,  s_a1);
    cudaGetSymbolAddress((void**)&p_nin, s_nin);
    cudaGetSymbolAddress((void**)&p_np1, s_np1);
    cudaGetSymbolAddress((void**)&p_np2, s_np2);
    cudaGetSymbolAddress((void**)&p_ein, s_ein);
    cudaGetSymbolAddress((void**)&p_ep1, s_ep1);
    cudaGetSymbolAddress((void**)&p_ep2, s_ep2);
    cudaGetSymbolAddress((void**)&p_sum, s_sum);
    cudaGetSymbolAddress((void**)&p_sq,  s_sq);

    const int GN  = (NN + 127) / 128;  // 157
    const int GTE = TE / 128;          // 2500

    k_zero<<<2048, 256>>>();
    k_detect<<<1, 32>>>((const int*)ei);
    k_decode<<<(NE + 255) / 256, 256>>>(ei);

    // lvl1 pieces: EW2 = er @ W[256:384], A0 = nr @ W[0:128], A1 = nr @ W[128:256]
    k_gemm<<<dim3(GTE, 1), 256>>>(er, lvl1_w + 256 * 128, p_ew2, TE, 128, 128, nullptr, nullptr);
    k_gemm<<<dim3(GN, 1),  256>>>(nr, lvl1_w,             p_a0,  NN, 128, 128, nullptr, nullptr);
    k_gemm<<<dim3(GN, 1),  256>>>(nr, lvl1_w + 128 * 128, p_a1,  NN, 128, 128, nullptr, nullptr);

    k_combine<<<2048, 128>>>(p_ew2);                       // stats slot 0
    k_scatter<<<2048, 128>>>(lvl1_g, lvl1_b, eps12);       // BN+ReLU + fused scatter

    // node path
    k_nin<<<4096, 256>>>(nr, eps11);
    k_gemm<<<dim3(GN, 2), 256>>>(p_nin, lvl2_w1, p_np1, NN, 128, 256, p_sum + 256, p_sq + 256);
    k_bnapply<<<4096, 256>>>(p_np1, p_np1, NN, 255, p_sum + 256, p_sq + 256, lvl2_g1, lvl2_b1);
    k_gemm<<<dim3(GN, 1), 256>>>(p_np1, lvl2_w2, p_np2, NN, 256, 128, p_sum + 512, p_sq + 512);
    k_bnapply<<<4096, 256>>>(p_np2, out_node, NN, 127, p_sum + 512, p_sq + 512, lvl2_g2, lvl2_b2);

    // edge path
    k_ein<<<2048, 128>>>(er, nr, eps2);
    k_gemm<<<dim3(GTE, 2), 256>>>(p_ein, lift_w1, p_ep1, TE, 256, 256, p_sum + 768, p_sq + 768);
    k_bnapply<<<8192, 256>>>(p_ep1, p_ep1, TE, 255, p_sum + 768, p_sq + 768, lift_g1, lift_b1);
    k_gemm<<<dim3(GTE, 1), 256>>>(p_ep1, lift_w2, p_ep2, TE, 256, 128, p_sum + 1024, p_sq + 1024);
    k_bnapply<<<8192, 256>>>(p_ep2, out_edge, TE, 127, p_sum + 1024, p_sq + 1024, lift_g2, lift_b2);
}

// round 2
// speedup vs baseline: 2.5928x; 2.5928x over previous
#include <cuda_runtime.h>

#define NN 20000      // nodes
#define NE 160000     // edges
#define TE 320000     // 2E edge-rows
#define HH 128

// ---------------- scratch (static __device__, no allocs) ----------------
__device__ __align__(128) float s_ew2 [(size_t)TE * 128];   // er @ W2
__device__ __align__(128) float s_a0  [(size_t)NN * 128];   // nr @ W0
__device__ __align__(128) float s_a1  [(size_t)NN * 128];   // nr @ W1
__device__ __align__(128) float s_pre1[(size_t)TE * 128];   // lvl1 pre-act
__device__ __align__(128) float s_nacc[(size_t)NN * 128];   // node scatter accum
__device__ __align__(128) float s_nin [(size_t)NN * 128];
__device__ __align__(128) float s_np1 [(size_t)NN * 256];   // raw pre-act
__device__ __align__(128) float s_np2 [(size_t)NN * 128];   // raw pre-act
__device__ __align__(128) float s_ein [(size_t)TE * 256];
__device__ __align__(128) float s_ep1 [(size_t)TE * 256];   // raw pre-act
__device__ __align__(128) float s_ep2 [(size_t)TE * 128];   // raw pre-act
__device__ float s_sum[5 * 256];
__device__ float s_sq [5 * 256];
__device__ int   s_u[NE];
__device__ int   s_v[NE];
__device__ int   g_is64;

// ---------------- helpers ----------------
__global__ void k_zero() {
    size_t stride = (size_t)gridDim.x * blockDim.x;
    size_t i0 = (size_t)blockIdx.x * blockDim.x + threadIdx.x;
    size_t n = (size_t)NN * 128;
    for (size_t i = i0; i < n; i += stride) s_nacc[i] = 0.0f;
    if (i0 < 5 * 256) { s_sum[i0] = 0.0f; s_sq[i0] = 0.0f; }
}

// edge_index may be int64 (high words all 0) or int32. Detect.
__global__ void k_detect(const int* __restrict__ ei32) {
    if (threadIdx.x == 0 && blockIdx.x == 0) {
        int nz = 0;
        for (int i = 0; i < 256; i++) nz |= ei32[2 * i + 1];
        g_is64 = (nz == 0) ? 1 : 0;
    }
}

__global__ void k_decode(const void* __restrict__ ei) {
    int e = blockIdx.x * blockDim.x + threadIdx.x;
    if (e >= NE) return;
    if (g_is64) {
        const long long* p = (const long long*)ei;
        s_u[e] = (int)p[e];
        s_v[e] = (int)p[NE + e];
    } else {
        const int* p = (const int*)ei;
        s_u[e] = p[e];
        s_v[e] = p[NE + e];
    }
}

__device__ __forceinline__ unsigned f2tf(float x) {
    unsigned r;
    asm("cvt.rna.tf32.f32 %0, %1;" : "=r"(r) : "f"(x));
    return r;
}

#define MMA_TF32(d, Af, Bf)                                                     \
    asm volatile(                                                               \
        "mma.sync.aligned.m16n8k8.row.col.f32.tf32.tf32.f32 "                   \
        "{%0,%1,%2,%3},{%4,%5,%6,%7},{%8,%9},{%0,%1,%2,%3};"                    \
        : "+f"(d[0]), "+f"(d[1]), "+f"(d[2]), "+f"(d[3])                        \
        : "r"(Af[0]), "r"(Af[1]), "r"(Af[2]), "r"(Af[3]),                       \
          "r"(Bf[0]), "r"(Bf[1]))

// ---------------- TF32 tensor-core GEMM, 128x128 tile, BK=32 ----------------
// C[M,NC] = relu_bn?(A)[M,K] @ B[K,NC]
//  - optional column sum/sumsq accumulation of C (for next BN)      [sumO/sqO]
//  - optional BN+ReLU applied to A on load (from producer's stats)  [aSum..aInv]
__global__ __launch_bounds__(256, 2) void k_mma(
    const float* __restrict__ A, const float* __restrict__ Bm,
    float* __restrict__ C, int M, int K, int NC,
    float* __restrict__ sumO, float* __restrict__ sqO,
    const float* __restrict__ aSum, const float* __restrict__ aSq,
    const float* __restrict__ aG, const float* __restrict__ aBt, float aInv)
{
    __shared__ unsigned As[128][36];   // row-major [m][k], pad 4
    __shared__ unsigned Bs[32][136];   // k-major  [k][n], pad 8
    __shared__ float scA[256], shA[256];

    const int tid = threadIdx.x;
    const int lane = tid & 31, warp = tid >> 5;
    const int group = lane >> 2, qt = lane & 3;
    const int warpM = warp & 1, warpN = warp >> 1;
    const int mBase = blockIdx.x * 128, nBase = blockIdx.y * 128;

    if (aG) {
        for (int k = tid; k < K; k += 256) {
            float mean = aSum[k] * aInv;
            float var  = aSq[k] * aInv - mean * mean;
            float s = aG[k] * rsqrtf(var + 1e-5f);
            scA[k] = s; shA[k] = aBt[k] - mean * s;
        }
        __syncthreads();
    }

    float acc[4][4][4];
#pragma unroll
    for (int mt = 0; mt < 4; mt++)
#pragma unroll
        for (int nt = 0; nt < 4; nt++)
#pragma unroll
            for (int i = 0; i < 4; i++) acc[mt][nt][i] = 0.0f;

    for (int k0 = 0; k0 < K; k0 += 32) {
        // A tile: 128x32, coalesced float4, optional BN+ReLU, cvt to tf32
#pragma unroll
        for (int it = 0; it < 4; it++) {
            int idx = tid + (it << 8);
            int row = idx >> 3, kq = (idx & 7) << 2;
            int gm = mBase + row, gk = k0 + kq;
            float4 v = make_float4(0.f, 0.f, 0.f, 0.f);
            if (gm < M) {
                v = *(const float4*)(A + (size_t)gm * K + gk);
                if (aG) {
                    v.x = fmaxf(fmaf(v.x, scA[gk + 0], shA[gk + 0]), 0.f);
                    v.y = fmaxf(fmaf(v.y, scA[gk + 1], shA[gk + 1]), 0.f);
                    v.z = fmaxf(fmaf(v.z, scA[gk + 2], shA[gk + 2]), 0.f);
                    v.w = fmaxf(fmaf(v.w, scA[gk + 3], shA[gk + 3]), 0.f);
                }
            }
            uint4 u;
            u.x = f2tf(v.x); u.y = f2tf(v.y); u.z = f2tf(v.z); u.w = f2tf(v.w);
            *(uint4*)&As[row][kq] = u;
        }
        // B tile: 32x128, coalesced float4
#pragma unroll
        for (int it = 0; it < 4; it++) {
            int idx = tid + (it << 8);
            int kr = idx >> 5, nc = (idx & 31) << 2;
            float4 v = *(const float4*)(Bm + (size_t)(k0 + kr) * NC + nBase + nc);
            uint4 u;
            u.x = f2tf(v.x); u.y = f2tf(v.y); u.z = f2tf(v.z); u.w = f2tf(v.w);
            *(uint4*)&Bs[kr][nc] = u;
        }
        __syncthreads();
#pragma unroll
        for (int ks = 0; ks < 4; ks++) {
            unsigned af[4][4], bf[4][2];
            int kc = ks * 8 + qt;
#pragma unroll
            for (int mt = 0; mt < 4; mt++) {
                int r = warpM * 64 + mt * 16 + group;
                af[mt][0] = As[r][kc];
                af[mt][1] = As[r + 8][kc];
                af[mt][2] = As[r][kc + 4];
                af[mt][3] = As[r + 8][kc + 4];
            }
#pragma unroll
            for (int nt = 0; nt < 4; nt++) {
                int cb = warpN * 32 + nt * 8 + group;
                bf[nt][0] = Bs[kc][cb];
                bf[nt][1] = Bs[kc + 4][cb];
            }
#pragma unroll
            for (int mt = 0; mt < 4; mt++)
#pragma unroll
                for (int nt = 0; nt < 4; nt++)
                    MMA_TF32(acc[mt][nt], af[mt], bf[nt]);
        }
        __syncthreads();
    }

    // epilogue: store + per-thread column partials (guard OOB rows)
    float cs[4][2], cq[4][2];
#pragma unroll
    for (int nt = 0; nt < 4; nt++) { cs[nt][0] = cs[nt][1] = 0.f; cq[nt][0] = cq[nt][1] = 0.f; }
#pragma unroll
    for (int mt = 0; mt < 4; mt++) {
        int r0 = mBase + warpM * 64 + mt * 16 + group;
        int r1 = r0 + 8;
#pragma unroll
        for (int nt = 0; nt < 4; nt++) {
            float c0 = acc[mt][nt][0], c1 = acc[mt][nt][1];
            float c2 = acc[mt][nt][2], c3 = acc[mt][nt][3];
            int cc = nBase + warpN * 32 + nt * 8 + 2 * qt;
            if (r0 < M) {
                float2 p = make_float2(c0, c1);
                *(float2*)(C + (size_t)r0 * NC + cc) = p;
                cs[nt][0] += c0; cs[nt][1] += c1;
                cq[nt][0] += c0 * c0; cq[nt][1] += c1 * c1;
            }
            if (r1 < M) {
                float2 p = make_float2(c2, c3);
                *(float2*)(C + (size_t)r1 * NC + cc) = p;
                cs[nt][0] += c2; cs[nt][1] += c3;
                cq[nt][0] += c2 * c2; cq[nt][1] += c3 * c3;
            }
        }
    }
    if (sumO) {
#pragma unroll
        for (int off = 4; off < 32; off <<= 1) {
#pragma unroll
            for (int nt = 0; nt < 4; nt++) {
#pragma unroll
                for (int p = 0; p < 2; p++) {
                    cs[nt][p] += __shfl_xor_sync(0xffffffffu, cs[nt][p], off);
                    cq[nt][p] += __shfl_xor_sync(0xffffffffu, cq[nt][p], off);
                }
            }
        }
        if (group == 0) {
#pragma unroll
            for (int nt = 0; nt < 4; nt++) {
                int cc = nBase + warpN * 32 + nt * 8 + 2 * qt;
                atomicAdd(sumO + cc,     cs[nt][0]);
                atomicAdd(sumO + cc + 1, cs[nt][1]);
                atomicAdd(sqO  + cc,     cq[nt][0]);
                atomicAdd(sqO  + cc + 1, cq[nt][1]);
            }
        }
    }
}

// pre1[2e]   = A0[u]+A0[v]+A1[u]+EW2[2e]
// pre1[2e+1] = A0[u]+A0[v]+A1[v]+EW2[2e+1]; accumulate BN stats (slot 0)
__global__ void k_combine(const float* __restrict__ ew2) {
    int c = threadIdx.x;  // 128
    float ls = 0.f, lq = 0.f;
    for (int e = blockIdx.x; e < NE; e += gridDim.x) {
        int u = s_u[e], v = s_v[e];
        float a0u = s_a0[(size_t)u * 128 + c], a0v = s_a0[(size_t)v * 128 + c];
        float a1u = s_a1[(size_t)u * 128 + c], a1v = s_a1[(size_t)v * 128 + c];
        float base = a0u + a0v;
        size_t r0 = (size_t)(2 * e) * 128, r1 = (size_t)(2 * e + 1) * 128;
        float p0 = base + a1u + ew2[r0 + c];
        float p1 = base + a1v + ew2[r1 + c];
        s_pre1[r0 + c] = p0;
        s_pre1[r1 + c] = p1;
        ls += p0 + p1; lq += p0 * p0 + p1 * p1;
    }
    atomicAdd(&s_sum[c], ls);
    atomicAdd(&s_sq[c],  lq);
}

// BN+ReLU on pre1, then scatter: nacc[u] += (1+eps12)*h0 + (h0+h1), sym for v
__global__ void k_scatter(const float* __restrict__ g, const float* __restrict__ b,
                          const float* __restrict__ eps12p) {
    int c = threadIdx.x;
    float mean = s_sum[c] * (1.0f / TE);
    float var  = s_sq[c]  * (1.0f / TE) - mean * mean;
    float sc = g[c] * rsqrtf(var + 1e-5f);
    float sh = b[c] - mean * sc;
    float e12 = 1.0f + *eps12p;
    for (int e = blockIdx.x; e < NE; e += gridDim.x) {
        int u = s_u[e], v = s_v[e];
        size_t r0 = (size_t)(2 * e) * 128, r1 = (size_t)(2 * e + 1) * 128;
        float h0 = fmaxf(s_pre1[r0 + c] * sc + sh, 0.f);
        float h1 = fmaxf(s_pre1[r1 + c] * sc + sh, 0.f);
        float ds = h0 + h1;
        atomicAdd(&s_nacc[(size_t)u * 128 + c], e12 * h0 + ds);
        atomicAdd(&s_nacc[(size_t)v * 128 + c], e12 * h1 + ds);
    }
}

__global__ void k_nin(const float* __restrict__ nr, const float* __restrict__ eps11p) {
    float e11 = 1.0f + *eps11p;
    size_t stride = (size_t)gridDim.x * blockDim.x;
    size_t n = (size_t)NN * 128;
    for (size_t i = (size_t)blockIdx.x * blockDim.x + threadIdx.x; i < n; i += stride)
        s_nin[i] = e11 * nr[i] + s_nacc[i];
}

// edge_in rows: [fh(e), sh(r)] with fh=(1+eps2)*0.5*(er0+er1)+nr[u]+nr[v], sh=(1+eps2)*er[r]+nr[atom]
__global__ void k_ein(const float* __restrict__ er, const float* __restrict__ nr,
                      const float* __restrict__ eps2p) {
    int c = threadIdx.x;
    float e2 = 1.0f + *eps2p;
    for (int e = blockIdx.x; e < NE; e += gridDim.x) {
        int u = s_u[e], v = s_v[e];
        size_t er0i = (size_t)(2 * e) * 128, er1i = (size_t)(2 * e + 1) * 128;
        float er0 = er[er0i + c], er1 = er[er1i + c];
        float nru = nr[(size_t)u * 128 + c], nrv = nr[(size_t)v * 128 + c];
        float fh = e2 * 0.5f * (er0 + er1) + nru + nrv;
        size_t r0 = (size_t)(2 * e) * 256, r1 = (size_t)(2 * e + 1) * 256;
        s_ein[r0 + c] = fh;
        s_ein[r1 + c] = fh;
        s_ein[r0 + 128 + c] = e2 * er0 + nru;
        s_ein[r1 + 128 + c] = e2 * er1 + nrv;
    }
}

// dst = relu(src*scale + shift), column stats from sum/sq (cols is a power of 2)
__global__ void k_bnapply(const float* __restrict__ src, float* __restrict__ dst,
                          int rows, int colMask,
                          const float* __restrict__ sum, const float* __restrict__ sq,
                          const float* __restrict__ g, const float* __restrict__ b) {
    float inv = 1.0f / (float)rows;
    size_t n = (size_t)rows * (colMask + 1);
    size_t stride = (size_t)gridDim.x * blockDim.x;
    for (size_t i = (size_t)blockIdx.x * blockDim.x + threadIdx.x; i < n; i += stride) {
        int c = (int)(i & (size_t)colMask);
        float mean = sum[c] * inv;
        float var  = sq[c] * inv - mean * mean;
        float sc = g[c] * rsqrtf(var + 1e-5f);
        float v = src[i] * sc + (b[c] - mean * sc);
        dst[i] = fmaxf(v, 0.f);
    }
}

// ---------------- launch ----------------
extern "C" void kernel_launch(void* const* d_in, const int* in_sizes, int n_in,
                              void* d_out, int out_size) {
    const float* nr      = (const float*)d_in[0];
    const float* er      = (const float*)d_in[1];
    const void*  ei      = d_in[2];
    const float* lift_w1 = (const float*)d_in[3];
    const float* lift_g1 = (const float*)d_in[4];
    const float* lift_b1 = (const float*)d_in[5];
    const float* lift_w2 = (const float*)d_in[6];
    const float* lift_g2 = (const float*)d_in[7];
    const float* lift_b2 = (const float*)d_in[8];
    const float* lvl1_w  = (const float*)d_in[9];
    const float* lvl1_g  = (const float*)d_in[10];
    const float* lvl1_b  = (const float*)d_in[11];
    const float* lvl2_w1 = (const float*)d_in[12];
    const float* lvl2_g1 = (const float*)d_in[13];
    const float* lvl2_b1 = (const float*)d_in[14];
    const float* lvl2_w2 = (const float*)d_in[15];
    const float* lvl2_g2 = (const float*)d_in[16];
    const float* lvl2_b2 = (const float*)d_in[17];
    const float* eps11   = (const float*)d_in[18];
    const float* eps12   = (const float*)d_in[19];
    const float* eps2    = (const float*)d_in[20];

    float* out_node = (float*)d_out;
    float* out_edge = out_node + (size_t)NN * HH;

    float *p_ew2, *p_a0, *p_a1, *p_nin, *p_np1, *p_np2, *p_ein, *p_ep1, *p_ep2, *p_sum, *p_sq;
    cudaGetSymbolAddress((void**)&p_ew2, s_ew2);
    cudaGetSymbolAddress((void**)&p_a0,  s_a0);
    cudaGetSymbolAddress((void**)&p_a1,  s_a1);
    cudaGetSymbolAddress((void**)&p_nin, s_nin);
    cudaGetSymbolAddress((void**)&p_np1, s_np1);
    cudaGetSymbolAddress((void**)&p_np2, s_np2);
    cudaGetSymbolAddress((void**)&p_ein, s_ein);
    cudaGetSymbolAddress((void**)&p_ep1, s_ep1);
    cudaGetSymbolAddress((void**)&p_ep2, s_ep2);
    cudaGetSymbolAddress((void**)&p_sum, s_sum);
    cudaGetSymbolAddress((void**)&p_sq,  s_sq);

    const int GN  = (NN + 127) / 128;  // 157
    const int GTE = TE / 128;          // 2500

    k_zero<<<2048, 256>>>();
    k_detect<<<1, 32>>>((const int*)ei);
    k_decode<<<(NE + 255) / 256, 256>>>(ei);

    // lvl1 pieces: EW2 = er @ W[256:384], A0 = nr @ W[0:128], A1 = nr @ W[128:256]
    k_mma<<<dim3(GTE, 1), 256>>>(er, lvl1_w + 256 * 128, p_ew2, TE, 128, 128,
                                 nullptr, nullptr, nullptr, nullptr, nullptr, nullptr, 0.f);
    k_mma<<<dim3(GN, 1),  256>>>(nr, lvl1_w,             p_a0,  NN, 128, 128,
                                 nullptr, nullptr, nullptr, nullptr, nullptr, nullptr, 0.f);
    k_mma<<<dim3(GN, 1),  256>>>(nr, lvl1_w + 128 * 128, p_a1,  NN, 128, 128,
                                 nullptr, nullptr, nullptr, nullptr, nullptr, nullptr, 0.f);

    k_combine<<<2048, 128>>>(p_ew2);                       // stats slot 0
    k_scatter<<<2048, 128>>>(lvl1_g, lvl1_b, eps12);       // BN+ReLU + fused scatter

    // node path: np1 raw + stats(slot1); np2 applies BN(slot1) on A-load, stats(slot2)
    k_nin<<<4096, 256>>>(nr, eps11);
    k_mma<<<dim3(GN, 2), 256>>>(p_nin, lvl2_w1, p_np1, NN, 128, 256,
                                p_sum + 256, p_sq + 256,
                                nullptr, nullptr, nullptr, nullptr, 0.f);
    k_mma<<<dim3(GN, 1), 256>>>(p_np1, lvl2_w2, p_np2, NN, 256, 128,
                                p_sum + 512, p_sq + 512,
                                p_sum + 256, p_sq + 256, lvl2_g1, lvl2_b1, 1.0f / NN);
    k_bnapply<<<4096, 256>>>(p_np2, out_node, NN, 127, p_sum + 512, p_sq + 512, lvl2_g2, lvl2_b2);

    // edge path: ep1 raw + stats(slot3); ep2 applies BN(slot3) on A-load, stats(slot4)
    k_ein<<<2048, 128>>>(er, nr, eps2);
    k_mma<<<dim3(GTE, 2), 256>>>(p_ein, lift_w1, p_ep1, TE, 256, 256,
                                 p_sum + 768, p_sq + 768,
                                 nullptr, nullptr, nullptr, nullptr, 0.f);
    k_mma<<<dim3(GTE, 1), 256>>>(p_ep1, lift_w2, p_ep2, TE, 256, 128,
                                 p_sum + 1024, p_sq + 1024,
                                 p_sum + 768, p_sq + 768, lift_g1, lift_b1, 1.0f / TE);
    k_bnapply<<<8192, 256>>>(p_ep2, out_edge, TE, 127, p_sum + 1024, p_sq + 1024, lift_g2, lift_b2);
}